// round 9
// baseline (speedup 1.0000x reference)
#include <cuda_runtime.h>
#include <cstdint>

// ============================================================================
// InstantNerf fused MLP, warp-level mma.sync fp16 (m16n8k16, fp32 acc), sm_103.
// R9: R8 + ldmatrix A-loads (4 LDS.32 -> 1 ldmatrix.x4) and fp16 position
// staged to smem so layer 1 uses the same path.
//  - CTA = 256 threads = 8 warps; each warp owns 32 samples, no barriers
//    after input staging.
//  - BUF row (stride 36 words): [pos 16w | dens 8w | SH 8w]; H row: 32w of 36.
//    36r mod 32 = 4r -> every ldmatrix 8-lane phase covers all 32 banks.
//  - Weights pre-packed to f16x2 B-fragment order in __device__ global (LDG).
// ============================================================================

static constexpr int THREADS = 256;
static constexpr int ROWS = 256;
static constexpr int ST = 36;    // row stride in 32-bit words for BUF and H

// smem word offsets
static constexpr int OFF_B1 = 0;      // 64 f32
static constexpr int OFF_B2 = 64;     // 16
static constexpr int OFF_B3 = 80;     // 64
static constexpr int OFF_B4 = 144;    // 64
static constexpr int OFF_B5 = 208;    // 8 (padded)
static constexpr int OFF_BUF = 224;                    // 256*36 = 9216
static constexpr int OFF_H   = OFF_BUF + ROWS * ST;    // 9440
static constexpr int SMEM_WORDS = OFF_H + ROWS * ST;   // 18656 -> 74624 B

// global fragment buffer (word offsets); slot s = ks16*NTtot + ntile, 64 words
static constexpr int W1F = 0;       // 2k x 8n x 64 = 1024
static constexpr int W2F = 1024;    // 4k x 2n x 64 = 512
static constexpr int W3F = 1536;    // 1024
static constexpr int W4F = 2560;    // 4k x 8n x 64 = 2048
static constexpr int W5F = 4608;    // 4k x 1n x 64 = 256
__device__ uint32_t g_wfrag[4864];

// pack two fp32 -> f16x2 (lo = first arg)
__device__ __forceinline__ uint32_t h2pack(float lo, float hi) {
    uint32_t r;
    asm("cvt.rn.f16x2.f32 %0, %1, %2;" : "=r"(r) : "f"(hi), "f"(lo));
    return r;
}

__device__ __forceinline__ void mma_f16(float (&d)[4], uint32_t a0, uint32_t a1,
                                        uint32_t a2, uint32_t a3,
                                        uint32_t b0, uint32_t b1) {
    asm volatile(
        "mma.sync.aligned.m16n8k16.row.col.f32.f16.f16.f32 "
        "{%0,%1,%2,%3}, {%4,%5,%6,%7}, {%8,%9}, {%0,%1,%2,%3};"
        : "+f"(d[0]), "+f"(d[1]), "+f"(d[2]), "+f"(d[3])
        : "r"(a0), "r"(a1), "r"(a2), "r"(a3), "r"(b0), "r"(b1));
}

__device__ __forceinline__ void ldmatrix_x4(uint32_t (&a)[4], uint32_t saddr) {
    asm volatile(
        "ldmatrix.sync.aligned.m8n8.x4.shared.b16 {%0,%1,%2,%3}, [%4];"
        : "=r"(a[0]), "=r"(a[1]), "=r"(a[2]), "=r"(a[3]) : "r"(saddr));
}

// ---------------- prep kernel: W[K][Nreal] -> f16x2 B-fragment order --------
__device__ __forceinline__ void stage_section(uint32_t* dst, const float* W,
                                              int Nreal, int KT, int NT,
                                              int tid, int ntot) {
    int total = KT * NT * 64;
    for (int idx = tid; idx < total; idx += ntot) {
        int s = idx >> 6, rem = idx & 63;
        int lane = rem >> 1, half = rem & 1;
        int ks = s / NT, nt = s - ks * NT;
        int g = lane >> 2, tg = lane & 3;
        int k0 = ks * 16 + half * 8 + 2 * tg;
        int nn = nt * 8 + g;
        float v0 = (nn < Nreal) ? W[k0 * Nreal + nn] : 0.0f;
        float v1 = (nn < Nreal) ? W[(k0 + 1) * Nreal + nn] : 0.0f;
        dst[s * 64 + lane * 2 + half] = h2pack(v0, v1);
    }
}

__global__ void prep_kernel(const float* __restrict__ W1, const float* __restrict__ W2,
                            const float* __restrict__ W3, const float* __restrict__ W4,
                            const float* __restrict__ W5) {
    int tid = blockIdx.x * blockDim.x + threadIdx.x;
    int ntot = gridDim.x * blockDim.x;
    stage_section(g_wfrag + W1F, W1, 64, 2, 8, tid, ntot);
    stage_section(g_wfrag + W2F, W2, 16, 4, 2, tid, ntot);
    stage_section(g_wfrag + W3F, W3, 64, 2, 8, tid, ntot);
    stage_section(g_wfrag + W4F, W4, 64, 8, 8, tid, ntot);   // note: W4 KT=4
    stage_section(g_wfrag + W5F, W5, 3, 4, 1, tid, ntot);
}

// ---------------- layer core (A via ldmatrix from smem fp16) ----------------
// abase: shared addr (bytes) of BUF/H + lane-dependent offset precomputed:
//   lane l -> row (l&7)+8*((l>>3)&1), colw 4*(l>>4); caller adds mrow0 and
//   per-layer column base.  Per (k,m): saddr = abase + (m*16*ST + k*8)*4.
template <int KT, int NT, int NTTOT>
__device__ __forceinline__ void run_layer(uint32_t abase,
                                          const uint2* __restrict__ bfrag,
                                          const float* __restrict__ bias,
                                          int tg, int lane,
                                          float (&acc)[2][NT][4]) {
#pragma unroll
    for (int m = 0; m < 2; m++)
#pragma unroll
        for (int nn = 0; nn < NT; nn++) {
            float2 bb = ((const float2*)bias)[nn * 4 + tg];
            acc[m][nn][0] = bb.x; acc[m][nn][1] = bb.y;
            acc[m][nn][2] = bb.x; acc[m][nn][3] = bb.y;
        }
#pragma unroll
    for (int k = 0; k < KT; k++) {
        uint2 bf[NT];
#pragma unroll
        for (int nn = 0; nn < NT; nn++)
            bf[nn] = bfrag[(k * NTTOT + nn) * 32 + lane];
#pragma unroll
        for (int m = 0; m < 2; m++) {
            uint32_t a[4];
            ldmatrix_x4(a, abase + (uint32_t)(m * 16 * ST + k * 8) * 4u);
#pragma unroll
            for (int nn = 0; nn < NT; nn++)
                mma_f16(acc[m][nn], a[0], a[1], a[2], a[3], bf[nn].x, bf[nn].y);
        }
    }
}

// relu + f16x2 pack + store (word stores, conflict-free)
template <int NT>
__device__ __forceinline__ void epi_relu_store(float (&acc)[2][NT][4],
                                               uint32_t* dst, int mrow0,
                                               int g, int tg) {
#pragma unroll
    for (int m = 0; m < 2; m++)
#pragma unroll
        for (int nn = 0; nn < NT; nn++) {
            int r0 = mrow0 + m * 16 + g;
            uint32_t lo = h2pack(fmaxf(acc[m][nn][0], 0.0f), fmaxf(acc[m][nn][1], 0.0f));
            uint32_t hi = h2pack(fmaxf(acc[m][nn][2], 0.0f), fmaxf(acc[m][nn][3], 0.0f));
            dst[r0 * ST + nn * 4 + tg] = lo;
            dst[(r0 + 8) * ST + nn * 4 + tg] = hi;
        }
}

__global__ void __launch_bounds__(THREADS, 2)
nerf_mma_kernel(const float* __restrict__ position,
                const float* __restrict__ direction,
                const float* __restrict__ b1, const float* __restrict__ b2,
                const float* __restrict__ b3, const float* __restrict__ b4,
                const float* __restrict__ b5,
                float* __restrict__ out, int n) {
    extern __shared__ float smf[];
    uint32_t* smu = (uint32_t*)smf;

    const int tid = threadIdx.x;
    const int lane = tid & 31;
    const int wid = tid >> 5;
    const int g = lane >> 2;
    const int tg = lane & 3;

    // biases (fp32)
    if (tid < 64) smf[OFF_B1 + tid] = b1[tid];
    if (tid < 16) smf[OFF_B2 + tid] = b2[tid];
    if (tid < 64) smf[OFF_B3 + tid] = b3[tid];
    if (tid < 64) smf[OFF_B4 + tid] = b4[tid];
    if (tid < 8)  smf[OFF_B5 + tid] = (tid < 3) ? b5[tid] : 0.0f;

    const int base = blockIdx.x * ROWS;
    uint32_t* BUF = smu + OFF_BUF;  // words 0-15 pos, 16-23 dens, 24-31 SH
    uint32_t* H   = smu + OFF_H;

    // ---- stage pos (fp16) + SH(dir) for own row ----
    {
        int r = base + tid; if (r >= n) r = n - 1;
        uint32_t* row = BUF + tid * ST;
        const float4* p4 = (const float4*)(position + (size_t)r * 32);
#pragma unroll
        for (int c = 0; c < 8; c++) {
            float4 v = p4[c];
            row[2 * c]     = h2pack(v.x, v.y);
            row[2 * c + 1] = h2pack(v.z, v.w);
        }
        const float* dp = direction + (size_t)r * 3;
        float x = dp[0], y = dp[1], z = dp[2];
        float xx = x * x, yy = y * y, zz = z * z;
        float sh[16];
        sh[0]  = 0.28209479177387814f;
        sh[1]  = 0.4886025119029199f * y;
        sh[2]  = 0.4886025119029199f * z;
        sh[3]  = 0.4886025119029199f * x;
        sh[4]  = 1.0925484305920792f * x * y;
        sh[5]  = 1.0925484305920792f * y * z;
        sh[6]  = 0.9461746957575601f * zz - 0.31539156525252f;
        sh[7]  = 1.0925484305920792f * x * z;
        sh[8]  = 0.5462742152960396f * (xx - yy);
        sh[9]  = 0.5900435899266435f * y * (3.0f * xx - yy);
        sh[10] = 2.890611442640554f * x * y * z;
        sh[11] = 0.4570457994644658f * y * (5.0f * zz - 1.0f);
        sh[12] = 0.3731763325901154f * z * (5.0f * zz - 3.0f);
        sh[13] = 0.4570457994644658f * x * (5.0f * zz - 1.0f);
        sh[14] = 1.445305721320277f * z * (xx - yy);
        sh[15] = 0.5900435899266435f * x * (xx - 3.0f * yy);
#pragma unroll
        for (int j = 0; j < 8; j++) row[24 + j] = h2pack(sh[2 * j], sh[2 * j + 1]);
    }
    __syncthreads();
    // Each warp now works only on its own 32 rows: no more barriers.

    const int mrow0 = wid * 32;
    const uint2* fr = (const uint2*)g_wfrag;

    // lane-dependent ldmatrix base offsets (bytes)
    const int trow = (lane & 7) + ((lane >> 3) & 1) * 8;
    const int tcolw = (lane >> 4) * 4;
    const uint32_t bufA = (uint32_t)__cvta_generic_to_shared(BUF) +
                          (uint32_t)((mrow0 + trow) * ST + tcolw) * 4u;
    const uint32_t hA = (uint32_t)__cvta_generic_to_shared(H) +
                        (uint32_t)((mrow0 + trow) * ST + tcolw) * 4u;

    // ---- L1: pos (BUF cols 0) @ W1 -> H (relu) ----
    {
        float acc[2][8][4];
        run_layer<2, 8, 8>(bufA, fr + (W1F >> 1), smf + OFF_B1, tg, lane, acc);
        epi_relu_store<8>(acc, H, mrow0, g, tg);
    }
    __syncwarp();

    // ---- L2: H @ W2 -> density (gmem fp32) + BUF words 16..23 ----
    {
        float acc[2][2][4];
        run_layer<4, 2, 2>(hA, fr + (W2F >> 1), smf + OFF_B2, tg, lane, acc);
#pragma unroll
        for (int m = 0; m < 2; m++)
#pragma unroll
            for (int nn = 0; nn < 2; nn++) {
                int r0 = mrow0 + m * 16 + g;
                int gr0 = base + r0;
                float2 lo = make_float2(acc[m][nn][0], acc[m][nn][1]);
                float2 hi = make_float2(acc[m][nn][2], acc[m][nn][3]);
                if (gr0 < n)
                    *(float2*)(out + (size_t)gr0 * 16 + nn * 8 + 2 * tg) = lo;
                if (gr0 + 8 < n)
                    *(float2*)(out + (size_t)(gr0 + 8) * 16 + nn * 8 + 2 * tg) = hi;
                BUF[r0 * ST + 16 + nn * 4 + tg] = h2pack(lo.x, lo.y);
                BUF[(r0 + 8) * ST + 16 + nn * 4 + tg] = h2pack(hi.x, hi.y);
            }
    }
    __syncwarp();

    // ---- L3: BUF cols 16.. (dens||SH) @ W3 -> H (relu) ----
    {
        float acc[2][8][4];
        run_layer<2, 8, 8>(bufA + 16 * 4, fr + (W3F >> 1), smf + OFF_B3,
                           tg, lane, acc);
        epi_relu_store<8>(acc, H, mrow0, g, tg);
    }
    __syncwarp();

    // ---- L4: H @ W4 -> H in place (safe: warp reads all before writing) ----
    {
        float acc[2][8][4];
        run_layer<4, 8, 8>(hA, fr + (W4F >> 1), smf + OFF_B4, tg, lane, acc);
        epi_relu_store<8>(acc, H, mrow0, g, tg);
    }
    __syncwarp();

    // ---- L5: H @ W5 -> color (sigmoid) ----
    {
        float acc[2][1][4];
        run_layer<4, 1, 1>(hA, fr + (W5F >> 1), smf + OFF_B5, tg, lane, acc);
        float* co = out + (size_t)n * 16;
#pragma unroll
        for (int m = 0; m < 2; m++) {
            int gr0 = base + mrow0 + m * 16 + g;
            float s0 = 1.0f / (1.0f + __expf(-acc[m][0][0]));
            float s1 = 1.0f / (1.0f + __expf(-acc[m][0][1]));
            float s2 = 1.0f / (1.0f + __expf(-acc[m][0][2]));
            float s3 = 1.0f / (1.0f + __expf(-acc[m][0][3]));
            if (tg == 0) {
                if (gr0 < n)     { co[(size_t)gr0 * 3 + 0] = s0;
                                   co[(size_t)gr0 * 3 + 1] = s1; }
                if (gr0 + 8 < n) { co[(size_t)(gr0 + 8) * 3 + 0] = s2;
                                   co[(size_t)(gr0 + 8) * 3 + 1] = s3; }
            } else if (tg == 1) {
                if (gr0 < n)     co[(size_t)gr0 * 3 + 2] = s0;
                if (gr0 + 8 < n) co[(size_t)(gr0 + 8) * 3 + 2] = s2;
            }
        }
    }
}

extern "C" void kernel_launch(void* const* d_in, const int* in_sizes, int n_in,
                              void* d_out, int out_size) {
    const float* position = (const float*)d_in[0];
    const float* direction = (const float*)d_in[1];
    const float* W1 = (const float*)d_in[2];
    const float* b1 = (const float*)d_in[3];
    const float* W2 = (const float*)d_in[4];
    const float* b2 = (const float*)d_in[5];
    const float* W3 = (const float*)d_in[6];
    const float* b3 = (const float*)d_in[7];
    const float* W4 = (const float*)d_in[8];
    const float* b4 = (const float*)d_in[9];
    const float* W5 = (const float*)d_in[10];
    const float* b5 = (const float*)d_in[11];
    float* out = (float*)d_out;

    int n = in_sizes[0] / 32;
    int ntiles = (n + ROWS - 1) / ROWS;
    if (ntiles <= 0) return;
    size_t smem_bytes = (size_t)SMEM_WORDS * 4;

    cudaFuncSetAttribute(nerf_mma_kernel,
                         cudaFuncAttributeMaxDynamicSharedMemorySize,
                         (int)smem_bytes);
    prep_kernel<<<20, 256>>>(W1, W2, W3, W4, W5);
    nerf_mma_kernel<<<ntiles, THREADS, smem_bytes>>>(position, direction,
                                                     b1, b2, b3, b4, b5,
                                                     out, n);
}

// round 12
// speedup vs baseline: 1.3204x; 1.3204x over previous
#include <cuda_runtime.h>
#include <cstdint>

// ============================================================================
// InstantNerf fused MLP, warp-level mma.sync fp16 (m16n8k16, fp32 acc), sm_103.
// R11 == R10 (round 10 hit an infra failure; design untested, resubmitting).
// Register-resident activation chaining: the m16n8k16 D-fragment layout
// equals the next layer's A-fragment layout, so L1->L2->L3->L4->L5 chain in
// registers (relu + f16x2 pack only). Only SH crosses smem (8 LDS/warp-tile).
//  - CTA = 128 threads = 4 warps; each warp owns 32 samples; no __syncthreads
//    except one for biases+SH.
//  - Weights pre-packed to f16x2 B-fragment order in __device__ global (LDG,
//    L1-resident ~19KB).
// ============================================================================

static constexpr int THREADS = 128;
static constexpr int ROWS = 128;
static constexpr int SHW = 12;   // SH row stride (words); (12g+tg) mod 32 all distinct

// smem word offsets
static constexpr int OFF_B1 = 0;      // 64 f32
static constexpr int OFF_B2 = 64;     // 16
static constexpr int OFF_B3 = 80;     // 64
static constexpr int OFF_B4 = 144;    // 64
static constexpr int OFF_B5 = 208;    // 8 (padded)
static constexpr int OFF_SH = 216;                    // 128*12 = 1536
static constexpr int SMEM_WORDS = OFF_SH + ROWS * SHW; // 1752 -> 7008 B

// global fragment buffer (word offsets); slot s = ks16*NTtot + ntile, 64 words
static constexpr int W1F = 0;       // 2k x 8n x 64 = 1024
static constexpr int W2F = 1024;    // 4k x 2n x 64 = 512
static constexpr int W3F = 1536;    // 2k x 8n x 64 = 1024
static constexpr int W4F = 2560;    // 4k x 8n x 64 = 2048
static constexpr int W5F = 4608;    // 4k x 1n x 64 = 256
__device__ uint32_t g_wfrag[4864];

__device__ __forceinline__ uint32_t h2pack(float lo, float hi) {
    uint32_t r;
    asm("cvt.rn.f16x2.f32 %0, %1, %2;" : "=r"(r) : "f"(hi), "f"(lo));
    return r;
}

__device__ __forceinline__ void mma_f16(float (&d)[4], uint32_t a0, uint32_t a1,
                                        uint32_t a2, uint32_t a3,
                                        uint32_t b0, uint32_t b1) {
    asm volatile(
        "mma.sync.aligned.m16n8k16.row.col.f32.f16.f16.f32 "
        "{%0,%1,%2,%3}, {%4,%5,%6,%7}, {%8,%9}, {%0,%1,%2,%3};"
        : "+f"(d[0]), "+f"(d[1]), "+f"(d[2]), "+f"(d[3])
        : "r"(a0), "r"(a1), "r"(a2), "r"(a3), "r"(b0), "r"(b1));
}

// ---------------- prep kernel: W[K][Nreal] -> f16x2 B-fragment order --------
__device__ __forceinline__ void stage_section(uint32_t* dst, const float* W,
                                              int Nreal, int KT, int NT,
                                              int tid, int ntot) {
    int total = KT * NT * 64;
    for (int idx = tid; idx < total; idx += ntot) {
        int s = idx >> 6, rem = idx & 63;
        int lane = rem >> 1, half = rem & 1;
        int ks = s / NT, nt = s - ks * NT;
        int g = lane >> 2, tg = lane & 3;
        int k0 = ks * 16 + half * 8 + 2 * tg;
        int nn = nt * 8 + g;
        float v0 = (nn < Nreal) ? W[k0 * Nreal + nn] : 0.0f;
        float v1 = (nn < Nreal) ? W[(k0 + 1) * Nreal + nn] : 0.0f;
        dst[s * 64 + lane * 2 + half] = h2pack(v0, v1);
    }
}

__global__ void prep_kernel(const float* __restrict__ W1, const float* __restrict__ W2,
                            const float* __restrict__ W3, const float* __restrict__ W4,
                            const float* __restrict__ W5) {
    int tid = blockIdx.x * blockDim.x + threadIdx.x;
    int ntot = gridDim.x * blockDim.x;
    stage_section(g_wfrag + W1F, W1, 64, 2, 8, tid, ntot);
    stage_section(g_wfrag + W2F, W2, 16, 4, 2, tid, ntot);
    stage_section(g_wfrag + W3F, W3, 64, 2, 8, tid, ntot);
    stage_section(g_wfrag + W4F, W4, 64, 4, 8, tid, ntot);
    stage_section(g_wfrag + W5F, W5, 3, 4, 1, tid, ntot);
}

// ---------------- layer core: A in registers ----------------
template <int KT, int NT, int NTTOT>
__device__ __forceinline__ void run_layer_reg(const uint32_t (&A)[2][KT][4],
                                              const uint2* __restrict__ bfrag,
                                              const float* __restrict__ bias,
                                              int tg, int lane,
                                              float (&acc)[2][NT][4]) {
#pragma unroll
    for (int m = 0; m < 2; m++)
#pragma unroll
        for (int nn = 0; nn < NT; nn++) {
            float2 bb = ((const float2*)bias)[nn * 4 + tg];
            acc[m][nn][0] = bb.x; acc[m][nn][1] = bb.y;
            acc[m][nn][2] = bb.x; acc[m][nn][3] = bb.y;
        }
#pragma unroll
    for (int k = 0; k < KT; k++) {
        uint2 bf[NT];
#pragma unroll
        for (int nn = 0; nn < NT; nn++)
            bf[nn] = bfrag[(k * NTTOT + nn) * 32 + lane];
#pragma unroll
        for (int m = 0; m < 2; m++)
#pragma unroll
            for (int nn = 0; nn < NT; nn++)
                mma_f16(acc[m][nn], A[m][k][0], A[m][k][1], A[m][k][2], A[m][k][3],
                        bf[nn].x, bf[nn].y);
    }
}

// relu + pack D-fragments (NT n-tiles) into A-fragments (NT/2 k-steps)
template <int NT>
__device__ __forceinline__ void relu_pack(const float (&acc)[2][NT][4],
                                          uint32_t (&A)[2][NT / 2][4]) {
#pragma unroll
    for (int m = 0; m < 2; m++)
#pragma unroll
        for (int k = 0; k < NT / 2; k++) {
            A[m][k][0] = h2pack(fmaxf(acc[m][2 * k][0], 0.0f), fmaxf(acc[m][2 * k][1], 0.0f));
            A[m][k][1] = h2pack(fmaxf(acc[m][2 * k][2], 0.0f), fmaxf(acc[m][2 * k][3], 0.0f));
            A[m][k][2] = h2pack(fmaxf(acc[m][2 * k + 1][0], 0.0f), fmaxf(acc[m][2 * k + 1][1], 0.0f));
            A[m][k][3] = h2pack(fmaxf(acc[m][2 * k + 1][2], 0.0f), fmaxf(acc[m][2 * k + 1][3], 0.0f));
        }
}

// L1: A from gmem position [n,32] fp32, converted inline (2 k16-steps)
__device__ __forceinline__ void run_layer1(const float* __restrict__ pos, int n,
                                           int rowbase,
                                           const uint2* __restrict__ bfrag,
                                           const float* __restrict__ bias,
                                           int g, int tg, int lane,
                                           float (&acc)[2][8][4]) {
#pragma unroll
    for (int m = 0; m < 2; m++)
#pragma unroll
        for (int nn = 0; nn < 8; nn++) {
            float2 bb = ((const float2*)bias)[nn * 4 + tg];
            acc[m][nn][0] = bb.x; acc[m][nn][1] = bb.y;
            acc[m][nn][2] = bb.x; acc[m][nn][3] = bb.y;
        }
    const float* pr[4];
#pragma unroll
    for (int m = 0; m < 2; m++) {
        int ra = rowbase + m * 16 + g;      if (ra >= n) ra = n - 1;
        int rb = rowbase + m * 16 + 8 + g;  if (rb >= n) rb = n - 1;
        pr[2 * m]     = pos + (size_t)ra * 32 + 2 * tg;
        pr[2 * m + 1] = pos + (size_t)rb * 32 + 2 * tg;
    }
#pragma unroll
    for (int k = 0; k < 2; k++) {
        uint2 bf[8];
#pragma unroll
        for (int nn = 0; nn < 8; nn++)
            bf[nn] = bfrag[(k * 8 + nn) * 32 + lane];
#pragma unroll
        for (int m = 0; m < 2; m++) {
            float2 va0 = *(const float2*)(pr[2 * m] + k * 16);
            float2 va1 = *(const float2*)(pr[2 * m + 1] + k * 16);
            float2 va2 = *(const float2*)(pr[2 * m] + k * 16 + 8);
            float2 va3 = *(const float2*)(pr[2 * m + 1] + k * 16 + 8);
            uint32_t a0 = h2pack(va0.x, va0.y);
            uint32_t a1 = h2pack(va1.x, va1.y);
            uint32_t a2 = h2pack(va2.x, va2.y);
            uint32_t a3 = h2pack(va3.x, va3.y);
#pragma unroll
            for (int nn = 0; nn < 8; nn++)
                mma_f16(acc[m][nn], a0, a1, a2, a3, bf[nn].x, bf[nn].y);
        }
    }
}

__global__ void __launch_bounds__(THREADS, 3)
nerf_mma_kernel(const float* __restrict__ position,
                const float* __restrict__ direction,
                const float* __restrict__ b1, const float* __restrict__ b2,
                const float* __restrict__ b3, const float* __restrict__ b4,
                const float* __restrict__ b5,
                float* __restrict__ out, int n) {
    extern __shared__ float smf[];
    uint32_t* smu = (uint32_t*)smf;

    const int tid = threadIdx.x;
    const int lane = tid & 31;
    const int wid = tid >> 5;
    const int g = lane >> 2;
    const int tg = lane & 3;

    // biases (fp32)
    if (tid < 64) smf[OFF_B1 + tid] = b1[tid];
    if (tid < 16) smf[OFF_B2 + tid] = b2[tid];
    if (tid < 64) smf[OFF_B3 + tid] = b3[tid];
    if (tid < 64) smf[OFF_B4 + tid] = b4[tid];
    if (tid < 8)  smf[OFF_B5 + tid] = (tid < 3) ? b5[tid] : 0.0f;

    const int base = blockIdx.x * ROWS;
    uint32_t* SH = smu + OFF_SH;

    // ---- SH(dir) for own row -> SH buffer (8 f16x2 words, stride 12) ----
    {
        int r = base + tid; if (r >= n) r = n - 1;
        const float* dp = direction + (size_t)r * 3;
        float x = dp[0], y = dp[1], z = dp[2];
        float xx = x * x, yy = y * y, zz = z * z;
        float sh[16];
        sh[0]  = 0.28209479177387814f;
        sh[1]  = 0.4886025119029199f * y;
        sh[2]  = 0.4886025119029199f * z;
        sh[3]  = 0.4886025119029199f * x;
        sh[4]  = 1.0925484305920792f * x * y;
        sh[5]  = 1.0925484305920792f * y * z;
        sh[6]  = 0.9461746957575601f * zz - 0.31539156525252f;
        sh[7]  = 1.0925484305920792f * x * z;
        sh[8]  = 0.5462742152960396f * (xx - yy);
        sh[9]  = 0.5900435899266435f * y * (3.0f * xx - yy);
        sh[10] = 2.890611442640554f * x * y * z;
        sh[11] = 0.4570457994644658f * y * (5.0f * zz - 1.0f);
        sh[12] = 0.3731763325901154f * z * (5.0f * zz - 3.0f);
        sh[13] = 0.4570457994644658f * x * (5.0f * zz - 1.0f);
        sh[14] = 1.445305721320277f * z * (xx - yy);
        sh[15] = 0.5900435899266435f * x * (xx - 3.0f * yy);
        uint32_t* row = SH + tid * SHW;
#pragma unroll
        for (int j = 0; j < 8; j++) row[j] = h2pack(sh[2 * j], sh[2 * j + 1]);
    }
    __syncthreads();   // biases + SH visible

    const int mrow0 = wid * 32;
    const uint2* fr = (const uint2*)g_wfrag;

    // ---- L1: pos @ W1 -> acc1; relu+pack -> A (reg) ----
    uint32_t A[2][4][4];
    {
        float acc1[2][8][4];
        run_layer1(position, n, base + mrow0, fr + (W1F >> 1), smf + OFF_B1,
                   g, tg, lane, acc1);
        relu_pack<8>(acc1, A);
    }

    // ---- L2: A @ W2 -> density; store gmem + pack AD (no relu) ----
    uint32_t AD[2][4];
    {
        float acc2[2][2][4];
        run_layer_reg<4, 2, 2>(A, fr + (W2F >> 1), smf + OFF_B2, tg, lane, acc2);
#pragma unroll
        for (int m = 0; m < 2; m++) {
            AD[m][0] = h2pack(acc2[m][0][0], acc2[m][0][1]);
            AD[m][1] = h2pack(acc2[m][0][2], acc2[m][0][3]);
            AD[m][2] = h2pack(acc2[m][1][0], acc2[m][1][1]);
            AD[m][3] = h2pack(acc2[m][1][2], acc2[m][1][3]);
#pragma unroll
            for (int nn = 0; nn < 2; nn++) {
                int gr0 = base + mrow0 + m * 16 + g;
                if (gr0 < n)
                    *(float2*)(out + (size_t)gr0 * 16 + nn * 8 + 2 * tg) =
                        make_float2(acc2[m][nn][0], acc2[m][nn][1]);
                if (gr0 + 8 < n)
                    *(float2*)(out + (size_t)(gr0 + 8) * 16 + nn * 8 + 2 * tg) =
                        make_float2(acc2[m][nn][2], acc2[m][nn][3]);
            }
        }
    }

    // ---- L3: [dens | SH] @ W3 -> acc3; relu+pack -> A ----
    {
        uint32_t A3[2][2][4];
#pragma unroll
        for (int m = 0; m < 2; m++) {
            A3[m][0][0] = AD[m][0]; A3[m][0][1] = AD[m][1];
            A3[m][0][2] = AD[m][2]; A3[m][0][3] = AD[m][3];
            int r0 = mrow0 + m * 16 + g;
            A3[m][1][0] = SH[r0 * SHW + tg];
            A3[m][1][1] = SH[(r0 + 8) * SHW + tg];
            A3[m][1][2] = SH[r0 * SHW + 4 + tg];
            A3[m][1][3] = SH[(r0 + 8) * SHW + 4 + tg];
        }
        float acc3[2][8][4];
        run_layer_reg<2, 8, 8>(A3, fr + (W3F >> 1), smf + OFF_B3, tg, lane, acc3);
        relu_pack<8>(acc3, A);
    }

    // ---- L4: A @ W4 -> acc4; relu+pack -> A ----
    {
        float acc4[2][8][4];
        run_layer_reg<4, 8, 8>(A, fr + (W4F >> 1), smf + OFF_B4, tg, lane, acc4);
        relu_pack<8>(acc4, A);
    }

    // ---- L5: A @ W5 -> color (sigmoid) ----
    {
        float acc5[2][1][4];
        run_layer_reg<4, 1, 1>(A, fr + (W5F >> 1), smf + OFF_B5, tg, lane, acc5);
        float* co = out + (size_t)n * 16;
#pragma unroll
        for (int m = 0; m < 2; m++) {
            int gr0 = base + mrow0 + m * 16 + g;
            float s0 = 1.0f / (1.0f + __expf(-acc5[m][0][0]));
            float s1 = 1.0f / (1.0f + __expf(-acc5[m][0][1]));
            float s2 = 1.0f / (1.0f + __expf(-acc5[m][0][2]));
            float s3 = 1.0f / (1.0f + __expf(-acc5[m][0][3]));
            if (tg == 0) {
                if (gr0 < n)     { co[(size_t)gr0 * 3 + 0] = s0;
                                   co[(size_t)gr0 * 3 + 1] = s1; }
                if (gr0 + 8 < n) { co[(size_t)(gr0 + 8) * 3 + 0] = s2;
                                   co[(size_t)(gr0 + 8) * 3 + 1] = s3; }
            } else if (tg == 1) {
                if (gr0 < n)     co[(size_t)gr0 * 3 + 2] = s0;
                if (gr0 + 8 < n) co[(size_t)(gr0 + 8) * 3 + 2] = s2;
            }
        }
    }
}

extern "C" void kernel_launch(void* const* d_in, const int* in_sizes, int n_in,
                              void* d_out, int out_size) {
    const float* position = (const float*)d_in[0];
    const float* direction = (const float*)d_in[1];
    const float* W1 = (const float*)d_in[2];
    const float* b1 = (const float*)d_in[3];
    const float* W2 = (const float*)d_in[4];
    const float* b2 = (const float*)d_in[5];
    const float* W3 = (const float*)d_in[6];
    const float* b3 = (const float*)d_in[7];
    const float* W4 = (const float*)d_in[8];
    const float* b4 = (const float*)d_in[9];
    const float* W5 = (const float*)d_in[10];
    const float* b5 = (const float*)d_in[11];
    float* out = (float*)d_out;

    int n = in_sizes[0] / 32;
    int ntiles = (n + ROWS - 1) / ROWS;
    if (ntiles <= 0) return;
    size_t smem_bytes = (size_t)SMEM_WORDS * 4;

    cudaFuncSetAttribute(nerf_mma_kernel,
                         cudaFuncAttributeMaxDynamicSharedMemorySize,
                         (int)smem_bytes);
    prep_kernel<<<20, 256>>>(W1, W2, W3, W4, W5);
    nerf_mma_kernel<<<ntiles, THREADS, smem_bytes>>>(position, direction,
                                                     b1, b2, b3, b4, b5,
                                                     out, n);
}